// round 4
// baseline (speedup 1.0000x reference)
#include <cuda_runtime.h>

#define BATCH   16
#define NPTS    4096
#define SPLIT   8
#define CTILE   (NPTS / SPLIT)   // 512 candidates per block
#define THREADS 256
#define PPT     4                // 4 x-points per thread = 2 packed pairs
#define NPAIR   (PPT / 2)

__device__ double       g_acc[2];
__device__ unsigned int g_min[2 * BATCH * NPTS];   // monotone-encoded fp32 mins

__device__ __forceinline__ unsigned int enc_f(float f) {
    unsigned int u = __float_as_uint(f);
    return (u & 0x80000000u) ? ~u : (u | 0x80000000u);
}
__device__ __forceinline__ float dec_f(unsigned int k) {
    unsigned int u = (k & 0x80000000u) ? (k & 0x7FFFFFFFu) : ~k;
    return __uint_as_float(u);
}
__device__ __forceinline__ unsigned long long pack2(float lo, float hi) {
    float2 f = make_float2(lo, hi);
    return *reinterpret_cast<unsigned long long*>(&f);
}

__global__ void init_kernel() {
    if (blockIdx.x == 0 && threadIdx.x < 2) g_acc[threadIdx.x] = 0.0;
    int total = 2 * BATCH * NPTS;
    for (int i = blockIdx.x * blockDim.x + threadIdx.x; i < total;
         i += gridDim.x * blockDim.x)
        g_min[i] = 0xFFFFFFFFu;
}

__global__ __launch_bounds__(THREADS) void chamfer_kernel(
    const float* __restrict__ xyz1, const float* __restrict__ xyz2)
{
    const int dir   = blockIdx.z >> 3;
    const int split = blockIdx.z & 7;
    const float* __restrict__ xs = (dir == 0) ? xyz1 : xyz2;
    const float* __restrict__ ys = (dir == 0) ? xyz2 : xyz1;
    const int b    = blockIdx.y;
    const int base = blockIdx.x * (THREADS * PPT);
    const int tid  = threadIdx.x;

    // Pre-duplicated packed candidate tiles:
    //   A = (-2x,-2x,-2y,-2y), B = (-2z,-2z,||y||^2,||y||^2)
    __shared__ float4 tileA[CTILE];
    __shared__ float4 tileB[CTILE];

    // Register-resident x-points, packed in pairs for f32x2 FMA.
    unsigned long long xq[NPAIR], yq[NPAIR], zq[NPAIR];
    float mn[PPT], sq1[PPT];
#pragma unroll
    for (int q = 0; q < NPAIR; q++) {
        int n0 = base + tid + (2 * q + 0) * THREADS;
        int n1 = base + tid + (2 * q + 1) * THREADS;
        const float* p0 = xs + ((size_t)b * NPTS + n0) * 3;
        const float* p1 = xs + ((size_t)b * NPTS + n1) * 3;
        float a0 = p0[0], b0 = p0[1], c0 = p0[2];
        float a1 = p1[0], b1 = p1[1], c1 = p1[2];
        xq[q] = pack2(a0, a1);
        yq[q] = pack2(b0, b1);
        zq[q] = pack2(c0, c1);
        sq1[2 * q + 0] = a0 * a0 + b0 * b0 + c0 * c0;
        sq1[2 * q + 1] = a1 * a1 + b1 * b1 + c1 * c1;
        mn[2 * q + 0] = 3.4e38f;
        mn[2 * q + 1] = 3.4e38f;
    }

    // Stage this block's candidate sub-range once (pre-packed, duplicated).
    {
        int c0 = split * CTILE;
#pragma unroll
        for (int j = 0; j < CTILE / THREADS; j++) {
            int ml = tid + j * THREADS;
            const float* yp = ys + ((size_t)b * NPTS + c0 + ml) * 3;
            float a = yp[0], c = yp[1], d = yp[2];
            float na = -2.0f * a, nc = -2.0f * c, nd = -2.0f * d;
            float sq = a * a + c * c + d * d;
            tileA[ml] = make_float4(na, na, nc, nc);
            tileB[ml] = make_float4(nd, nd, sq, sq);
        }
    }
    __syncthreads();

#pragma unroll 4
    for (int i = 0; i < CTILE; i++) {
        ulonglong2 A  = *reinterpret_cast<const ulonglong2*>(&tileA[i]);
        ulonglong2 Bv = *reinterpret_cast<const ulonglong2*>(&tileB[i]);
#pragma unroll
        for (int q = 0; q < NPAIR; q++) {
            unsigned long long r;
            // Single asm block: no tied-operand register-pair copies.
            asm("{\n\t"
                ".reg .b64 t;\n\t"
                "fma.rn.f32x2 t, %1, %2, %3;\n\t"
                "fma.rn.f32x2 t, %4, %5, t;\n\t"
                "fma.rn.f32x2 %0, %6, %7, t;\n\t"
                "}"
                : "=l"(r)
                : "l"(zq[q]), "l"(Bv.x), "l"(Bv.y),
                  "l"(yq[q]), "l"(A.y),
                  "l"(xq[q]), "l"(A.x));
            float2 rf = *reinterpret_cast<float2*>(&r);
            mn[2 * q + 0] = fminf(mn[2 * q + 0], rf.x);
            mn[2 * q + 1] = fminf(mn[2 * q + 1], rf.y);
        }
    }

    // Combine partial mins across candidate-splits.
    unsigned int* row = g_min + ((dir * BATCH + b) << 12);
#pragma unroll
    for (int p = 0; p < PPT; p++) {
        int n = base + tid + p * THREADS;
        atomicMin(&row[n], enc_f(mn[p] + sq1[p]));
    }
}

__global__ __launch_bounds__(THREADS) void reduce_kernel() {
    const int row = blockIdx.x;
    const int dir = row >> 4;
    const unsigned int* src = g_min + (row << 12);
    const int tid = threadIdx.x;

    float s = 0.0f;
#pragma unroll
    for (int j = 0; j < NPTS / THREADS; j++)
        s += dec_f(src[tid + j * THREADS]);

    __shared__ float red[THREADS / 32];
#pragma unroll
    for (int o = 16; o > 0; o >>= 1) s += __shfl_down_sync(0xffffffffu, s, o);
    if ((tid & 31) == 0) red[tid >> 5] = s;
    __syncthreads();
    if (tid < THREADS / 32) {
        s = red[tid];
#pragma unroll
        for (int o = (THREADS / 64); o > 0; o >>= 1)
            s += __shfl_down_sync(0xffu, s, o);
        if (tid == 0) atomicAdd(&g_acc[dir], (double)s);
    }
}

__global__ void finalize_kernel(float* out) {
    if (threadIdx.x < 2)
        out[threadIdx.x] = (float)(g_acc[threadIdx.x] / (double)(BATCH * NPTS));
}

extern "C" void kernel_launch(void* const* d_in, const int* in_sizes, int n_in,
                              void* d_out, int out_size)
{
    const float* xyz1 = (const float*)d_in[0];
    const float* xyz2 = (const float*)d_in[1];
    float* out = (float*)d_out;

    init_kernel<<<128, 256>>>();
    dim3 grid(NPTS / (THREADS * PPT), BATCH, 2 * SPLIT);   // 1024 blocks
    chamfer_kernel<<<grid, THREADS>>>(xyz1, xyz2);
    reduce_kernel<<<2 * BATCH, THREADS>>>();
    finalize_kernel<<<1, 32>>>(out);
}